// round 6
// baseline (speedup 1.0000x reference)
#include <cuda_runtime.h>
#include <cuda_bf16.h>
#include <cstdint>

// ---------------------------------------------------------------------------
// BVP Helmholtz residual via 2nd-order jet propagation on mma.sync bf16 HMMA
// (3-pass hi/lo split). Round 6: 256 threads, M=64 (12 samples/CTA), smem
// 109.2KB -> 2 CTAs/SM so epilogue/barrier phases of one CTA overlap the MMA
// mainloop of the other. B staged in k=16 chunks with hi/lo interleaved per
// row (80B stride, conflict-free), double buffered. D aliases dead A rows.
// ---------------------------------------------------------------------------

#define HD 256
#define SB 12          // samples per CTA
#define AROW 1040      // A row bytes: hi[0,512) pad lo[528,1040) == D row
#define BROW 80        // B row: hi k16 (32B) + lo k16 (32B) + 16B pad
#define BBUF 20480     // 256*80 per buffer (both splits, k=16)
#define DROW 260       // D row stride in floats (= 1040 B)
#define NKC 16         // k-chunks of 16 per layer

#define A_OFF 0
#define B_OFF 66560    // 64*1040
#define XYZF_OFF 107520
#define PART_OFF 107712
#define SMEM_BYTES 109248

// prepped weights: [layer][split hi/lo][n][k] bf16
__device__ __align__(16) __nv_bfloat16 Wbf[2][2][HD][HD];

__global__ __launch_bounds__(256)
void prep_weights(const float* __restrict__ W2, const float* __restrict__ W3)
{
    int t = blockIdx.x * 256 + threadIdx.x;      // 131072
    int layer = t >> 16, n = (t >> 8) & 255, k = t & 255;
    float w = (layer ? W3 : W2)[n * HD + k];
    __nv_bfloat16 h = __float2bfloat16(w);
    __nv_bfloat16 l = __float2bfloat16(w - __bfloat162float(h));
    Wbf[layer][0][n][k] = h;
    Wbf[layer][1][n][k] = l;
}

__device__ __forceinline__ uint32_t smem_u32(const void* p) {
    uint32_t a;
    asm("{ .reg .u64 t; cvta.to.shared.u64 t, %1; cvt.u32.u64 %0, t; }"
        : "=r"(a) : "l"(p));
    return a;
}
__device__ __forceinline__ void ldsm4(uint32_t* r, uint32_t a) {
    asm volatile("ldmatrix.sync.aligned.m8n8.x4.shared.b16 {%0,%1,%2,%3}, [%4];"
                 : "=r"(r[0]), "=r"(r[1]), "=r"(r[2]), "=r"(r[3]) : "r"(a));
}
__device__ __forceinline__ void ldsm2(uint32_t* r, uint32_t a) {
    asm volatile("ldmatrix.sync.aligned.m8n8.x2.shared.b16 {%0,%1}, [%2];"
                 : "=r"(r[0]), "=r"(r[1]) : "r"(a));
}
__device__ __forceinline__ void mma_bf16(float* c, const uint32_t* a,
                                         const uint32_t* b) {
    asm volatile("mma.sync.aligned.m16n8k16.row.col.f32.bf16.bf16.f32 "
                 "{%0,%1,%2,%3}, {%4,%5,%6,%7}, {%8,%9}, {%0,%1,%2,%3};"
                 : "+f"(c[0]), "+f"(c[1]), "+f"(c[2]), "+f"(c[3])
                 : "r"(a[0]), "r"(a[1]), "r"(a[2]), "r"(a[3]),
                   "r"(b[0]), "r"(b[1]));
}
__device__ __forceinline__ void cp16(uint32_t sa, const void* ga) {
    asm volatile("cp.async.cg.shared.global [%0], [%1], 16;"
                 :: "r"(sa), "l"(__cvta_generic_to_global(ga)) : "memory");
}
#define CP_COMMIT() asm volatile("cp.async.commit_group;" ::: "memory")
#define CP_WAIT(n)  asm volatile("cp.async.wait_group %0;" :: "n"(n) : "memory")

__global__ __launch_bounds__(256, 2)
void bvp_mma_kernel(const float* __restrict__ gx, const float* __restrict__ gy,
                    const float* __restrict__ gz, const float* __restrict__ gf,
                    const float* __restrict__ W1, const float* __restrict__ b1,
                    const float* __restrict__ b2, const float* __restrict__ b3,
                    const float* __restrict__ W4, const float* __restrict__ b4,
                    float* __restrict__ out, int N)
{
    extern __shared__ char sm[];
    const uint32_t smb = smem_u32(sm);
    float* Dst  = (float*)(sm + A_OFF);       // aliases A region, row-for-row
    float* xyzf = (float*)(sm + XYZF_OFF);
    float* part = (float*)(sm + PART_OFF);    // [12][8][4]

    const int tid = threadIdx.x;
    const int wid = tid >> 5;
    const int lid = tid & 31;
    const int n0w = wid << 5;                 // n-slice (8 warps x 32)
    const int n0  = blockIdx.x * SB;

    const float CX = (float)((0.5 * 0.6) * (0.5 * 0.6));
    const float CY = (float)((0.7 * 0.6) * (0.7 * 0.6));
    const float CZ = (float)((0.7 * 0.5) * (0.7 * 0.5));

    // stage one k=16 chunk of layer L's B into buffer (hi/lo interleaved rows)
    auto issue_stage = [&](int L, int kc, int buf) {
        #pragma unroll
        for (int j = 0; j < 4; ++j) {
            int split = j >> 1, half = j & 1;
            uint32_t sa = smb + B_OFF + buf * BBUF + tid * BROW +
                          split * 32 + half * 16;
            cp16(sa, &Wbf[L][split][tid][kc * 16 + half * 8]);
        }
        CP_COMMIT();
    };

    auto storeA = [&](int m, int k, float v) {
        __nv_bfloat16 h = __float2bfloat16(v);
        __nv_bfloat16 l = __float2bfloat16(v - __bfloat162float(h));
        char* base = sm + A_OFF + m * AROW + k * 2;
        *(__nv_bfloat16*)(base)       = h;
        *(__nv_bfloat16*)(base + 528) = l;
    };

    // prefetch first two B stages of layer 0
    issue_stage(0, 0, 0);
    issue_stage(0, 1, 1);

    // coords
    if (tid < 48) {
        int ss = tid >> 2, w = tid & 3;
        int n = n0 + ss; if (n >= N) n = N - 1;
        const float* p = (w == 0) ? gx : (w == 1) ? gy : (w == 2) ? gz : gf;
        xyzf[tid] = p[n];
    }
    // zero pad rows 60..63 of A (both splits)
    #pragma unroll
    for (int j = 0; j < 4; ++j) {
        int i = tid + (j << 8);
        int m = 60 + (i >> 8), k = i & 255;
        storeA(m, k, 0.0f);
    }
    __syncthreads();

    // ---- layer 1: 4 -> 256, jets analytically ------------------------------
    #pragma unroll 1
    for (int s = 0; s < SB; ++s) {
        int k = tid;
        float4 w = *(const float4*)(W1 + k * 4);
        float u = fmaf(w.x, xyzf[s * 4 + 0], fmaf(w.y, xyzf[s * 4 + 1],
                  fmaf(w.z, xyzf[s * 4 + 2], fmaf(w.w, xyzf[s * 4 + 3],
                  b1[k]))));
        float yv = tanhf(u);
        float sg = fmaf(-yv, yv, 1.0f);
        float g  = CX * w.x * w.x + CY * w.y * w.y + CZ * w.z * w.z;
        int m = s * 5;
        storeA(m + 0, k, yv);
        storeA(m + 1, k, sg * w.x);
        storeA(m + 2, k, sg * w.y);
        storeA(m + 3, k, sg * w.z);
        storeA(m + 4, k, -2.0f * yv * sg * g);
    }
    __syncthreads();

    const int g = lid >> 2, cc = (lid & 3) << 1;

    // ---- hidden layers 2,3 --------------------------------------------------
    #pragma unroll 1
    for (int L = 0; L < 2; ++L) {
        float acc[4][4][4];
        #pragma unroll
        for (int mt = 0; mt < 4; ++mt)
            #pragma unroll
            for (int nt = 0; nt < 4; ++nt)
                #pragma unroll
                for (int r = 0; r < 4; ++r) acc[mt][nt][r] = 0.f;

        #pragma unroll 1
        for (int kc = 0; kc < NKC; ++kc) {
            if (L == 1 && kc == NKC - 1) { CP_WAIT(0); } else { CP_WAIT(1); }
            __syncthreads();
            int buf = kc & 1;

            // B fragments: hi at +0, lo at +32 within the row
            uint32_t bf[2][4][2];
            #pragma unroll
            for (int nt = 0; nt < 4; ++nt) {
                uint32_t ba = smb + B_OFF + buf * BBUF +
                              (n0w + (nt << 3) + (lid & 7)) * BROW +
                              (lid & 8) * 2;
                ldsm2(bf[0][nt], ba);
                ldsm2(bf[1][nt], ba + 32);
            }
            #pragma unroll
            for (int mt = 0; mt < 4; ++mt) {
                int row = (mt << 4) + (lid & 15);
                uint32_t aa = smb + A_OFF + row * AROW +
                              (kc * 16 + ((lid >> 4) << 3)) * 2;
                uint32_t ah[4], al[4];
                ldsm4(ah, aa);
                ldsm4(al, aa + 528);
                #pragma unroll
                for (int nt = 0; nt < 4; ++nt) {
                    mma_bf16(acc[mt][nt], ah, bf[0][nt]);  // hi*hi
                    mma_bf16(acc[mt][nt], al, bf[0][nt]);  // lo*hi
                    mma_bf16(acc[mt][nt], ah, bf[1][nt]);  // hi*lo
                }
            }
            __syncthreads();
            if (kc + 2 < NKC)    issue_stage(L, kc + 2, buf);
            else if (L == 0)     issue_stage(1, kc - (NKC - 2), buf);
        }

        // ---- stage acc into D (aliases dead A rows) --------------------------
        #pragma unroll
        for (int mt = 0; mt < 4; ++mt)
            #pragma unroll
            for (int nt = 0; nt < 4; ++nt) {
                int m0 = (mt << 4), nn = n0w + (nt << 3) + cc;
                *(float2*)(Dst + (m0 + g) * DROW + nn) =
                    make_float2(acc[mt][nt][0], acc[mt][nt][1]);
                *(float2*)(Dst + (m0 + g + 8) * DROW + nn) =
                    make_float2(acc[mt][nt][2], acc[mt][nt][3]);
            }
        __syncthreads();

        // ---- activation epilogue (in-place D -> new A exchange) --------------
        const int nn = tid;
        if (L == 0) {
            float bn = b2[nn];
            #pragma unroll 1
            for (int s = 0; s < SB; ++s) {
                int mr = s * 5;
                float u  = Dst[(mr + 0) * DROW + nn] + bn;
                float tx = Dst[(mr + 1) * DROW + nn];
                float ty = Dst[(mr + 2) * DROW + nn];
                float tz = Dst[(mr + 3) * DROW + nn];
                float qa = Dst[(mr + 4) * DROW + nn];
                __syncthreads();           // all reads of these rows done
                float yv = tanhf(u);
                float sgm = fmaf(-yv, yv, 1.0f);
                float gq = CX * tx * tx + CY * ty * ty + CZ * tz * tz;
                storeA(mr + 0, nn, yv);
                storeA(mr + 1, nn, sgm * tx);
                storeA(mr + 2, nn, sgm * ty);
                storeA(mr + 3, nn, sgm * tz);
                storeA(mr + 4, nn, fmaf(sgm, qa, -2.0f * yv * sgm * gq));
            }
            __syncthreads();
        } else {
            float bn  = b3[nn];
            float w40 = W4[nn], w41 = W4[HD + nn];
            #pragma unroll 1
            for (int s = 0; s < SB; ++s) {
                int mr = s * 5;
                float u  = Dst[(mr + 0) * DROW + nn] + bn;
                float tx = Dst[(mr + 1) * DROW + nn];
                float ty = Dst[(mr + 2) * DROW + nn];
                float tz = Dst[(mr + 3) * DROW + nn];
                float qa = Dst[(mr + 4) * DROW + nn];
                float yv = tanhf(u);
                float sgm = fmaf(-yv, yv, 1.0f);
                float gq = CX * tx * tx + CY * ty * ty + CZ * tz * tz;
                float qn = fmaf(sgm, qa, -2.0f * yv * sgm * gq);
                float v0 = w40 * yv, v1 = w41 * yv;
                float v2 = w40 * qn, v3 = w41 * qn;
                #pragma unroll
                for (int o = 16; o; o >>= 1) {
                    v0 += __shfl_xor_sync(0xFFFFFFFFu, v0, o);
                    v1 += __shfl_xor_sync(0xFFFFFFFFu, v1, o);
                    v2 += __shfl_xor_sync(0xFFFFFFFFu, v2, o);
                    v3 += __shfl_xor_sync(0xFFFFFFFFu, v3, o);
                }
                if (lid == 0) {
                    float* pp = part + (s * 8 + wid) * 4;
                    pp[0] = v0; pp[1] = v1; pp[2] = v2; pp[3] = v3;
                }
            }
            __syncthreads();
        }
    }

    // ---- residual output -----------------------------------------------------
    if (tid < SB) {
        int n = n0 + tid;
        if (n < N) {
            float P0 = 0.f, P1 = 0.f, Q0 = 0.f, Q1 = 0.f;
            #pragma unroll
            for (int w = 0; w < 8; ++w) {
                const float* pp = part + (tid * 8 + w) * 4;
                P0 += pp[0]; P1 += pp[1]; Q0 += pp[2]; Q1 += pp[3];
            }
            P0 += b4[0]; P1 += b4[1];
            float fs = xyzf[tid * 4 + 3];
            float kw = 6.283185307179586f * fmaf(fs, 500.0f, 100.0f) / 343.0f;
            float kx = 0.21f * kw;
            float K2 = kx * kx;
            out[n]     = 2.0f * Q0 + K2 * fmaf(2.0f, P0, 0.1f);
            out[N + n] = 1.5f * Q1 + K2 * fmaf(1.5f, P1, -0.05f);
        }
    }
}

extern "C" void kernel_launch(void* const* d_in, const int* in_sizes, int n_in,
                              void* d_out, int out_size)
{
    const float* x  = (const float*)d_in[0];
    const float* y  = (const float*)d_in[1];
    const float* z  = (const float*)d_in[2];
    const float* f  = (const float*)d_in[3];
    const float* W1 = (const float*)d_in[4];
    const float* b1 = (const float*)d_in[5];
    const float* W2 = (const float*)d_in[6];
    const float* b2 = (const float*)d_in[7];
    const float* W3 = (const float*)d_in[8];
    const float* b3 = (const float*)d_in[9];
    const float* W4 = (const float*)d_in[10];
    const float* b4 = (const float*)d_in[11];
    float* out = (float*)d_out;

    int N = in_sizes[0];
    prep_weights<<<512, 256>>>(W2, W3);

    cudaFuncSetAttribute(bvp_mma_kernel,
                         cudaFuncAttributeMaxDynamicSharedMemorySize,
                         SMEM_BYTES);
    int blocks = (N + SB - 1) / SB;
    bvp_mma_kernel<<<blocks, 256, SMEM_BYTES>>>(x, y, z, f, W1, b1, b2, b3,
                                                W4, b4, out, N);
}

// round 7
// speedup vs baseline: 1.2839x; 1.2839x over previous
#include <cuda_runtime.h>
#include <cuda_bf16.h>
#include <cstdint>

// ---------------------------------------------------------------------------
// BVP Helmholtz residual via 2nd-order jet propagation on mma.sync bf16 HMMA
// (3-pass hi/lo split). Round 7: 512 threads, M=96 (19 samples/CTA),
// 3-deep B stage ring -> ONE barrier per k-chunk (16 mainloop barriers/CTA
// instead of 32). D staging aliases dead A rows (in-place jet exchange).
// ---------------------------------------------------------------------------

#define HD 256
#define SB 19          // samples per CTA (95 jet rows + 1 pad = M 96)
#define MT 3           // m-tiles of 16 per m-group (2 groups x 48 rows)
#define AROW 1040      // A row bytes: hi[0,512) pad lo[528,1040) == D row
#define BROW 80        // B stage row stride bytes (32 k bf16 + pad)
#define BSPLIT 20480   // 256*80
#define BBUF 40960     // per stage buffer (2 splits)
#define DROW 260       // D row stride in floats (= 1040 B)
#define NKC 8          // k-chunks of 32 per layer

#define A_OFF 0
#define B_OFF 99840    // 96*1040
#define XYZF_OFF 222720
#define PART_OFF 223040
#define SMEM_BYTES 225472

// prepped weights: [layer][split hi/lo][n][k] bf16
__device__ __align__(16) __nv_bfloat16 Wbf[2][2][HD][HD];

__global__ __launch_bounds__(256)
void prep_weights(const float* __restrict__ W2, const float* __restrict__ W3)
{
    int t = blockIdx.x * 256 + threadIdx.x;      // 131072
    int layer = t >> 16, n = (t >> 8) & 255, k = t & 255;
    float w = (layer ? W3 : W2)[n * HD + k];
    __nv_bfloat16 h = __float2bfloat16(w);
    __nv_bfloat16 l = __float2bfloat16(w - __bfloat162float(h));
    Wbf[layer][0][n][k] = h;
    Wbf[layer][1][n][k] = l;
}

__device__ __forceinline__ uint32_t smem_u32(const void* p) {
    uint32_t a;
    asm("{ .reg .u64 t; cvta.to.shared.u64 t, %1; cvt.u32.u64 %0, t; }"
        : "=r"(a) : "l"(p));
    return a;
}
__device__ __forceinline__ void ldsm4(uint32_t* r, uint32_t a) {
    asm volatile("ldmatrix.sync.aligned.m8n8.x4.shared.b16 {%0,%1,%2,%3}, [%4];"
                 : "=r"(r[0]), "=r"(r[1]), "=r"(r[2]), "=r"(r[3]) : "r"(a));
}
__device__ __forceinline__ void ldsm2(uint32_t* r, uint32_t a) {
    asm volatile("ldmatrix.sync.aligned.m8n8.x2.shared.b16 {%0,%1}, [%2];"
                 : "=r"(r[0]), "=r"(r[1]) : "r"(a));
}
__device__ __forceinline__ void mma_bf16(float* c, const uint32_t* a,
                                         const uint32_t* b) {
    asm volatile("mma.sync.aligned.m16n8k16.row.col.f32.bf16.bf16.f32 "
                 "{%0,%1,%2,%3}, {%4,%5,%6,%7}, {%8,%9}, {%0,%1,%2,%3};"
                 : "+f"(c[0]), "+f"(c[1]), "+f"(c[2]), "+f"(c[3])
                 : "r"(a[0]), "r"(a[1]), "r"(a[2]), "r"(a[3]),
                   "r"(b[0]), "r"(b[1]));
}
__device__ __forceinline__ void cp16(uint32_t sa, const void* ga) {
    asm volatile("cp.async.cg.shared.global [%0], [%1], 16;"
                 :: "r"(sa), "l"(__cvta_generic_to_global(ga)) : "memory");
}
#define CP_COMMIT() asm volatile("cp.async.commit_group;" ::: "memory")
#define CP_WAIT(n)  asm volatile("cp.async.wait_group %0;" :: "n"(n) : "memory")

__global__ __launch_bounds__(512, 1)
void bvp_mma_kernel(const float* __restrict__ gx, const float* __restrict__ gy,
                    const float* __restrict__ gz, const float* __restrict__ gf,
                    const float* __restrict__ W1, const float* __restrict__ b1,
                    const float* __restrict__ b2, const float* __restrict__ b3,
                    const float* __restrict__ W4, const float* __restrict__ b4,
                    float* __restrict__ out, int N)
{
    extern __shared__ char sm[];
    const uint32_t smb = smem_u32(sm);
    float* Dst  = (float*)(sm + A_OFF);       // aliases A region, row-for-row
    float* xyzf = (float*)(sm + XYZF_OFF);
    float* part = (float*)(sm + PART_OFF);    // [19][8][4]

    const int tid = threadIdx.x;
    const int wid = tid >> 5;
    const int lid = tid & 31;
    const int mg  = wid >> 3;                 // m-group 0/1 (rows mg*48..+48)
    const int ng  = wid & 7;                  // n-slice (cols ng*32..+32)
    const int n0w = ng << 5;
    const int n0  = blockIdx.x * SB;

    const float CX = (float)((0.5 * 0.6) * (0.5 * 0.6));
    const float CY = (float)((0.7 * 0.6) * (0.7 * 0.6));
    const float CZ = (float)((0.7 * 0.5) * (0.7 * 0.5));

    // stage one k=32 chunk of layer L's B into ring buffer `buf`
    auto issue_stage = [&](int L, int kc, int buf) {
        #pragma unroll
        for (int j = 0; j < 4; ++j) {
            int i = tid + (j << 9);              // 0..2047
            int split = i >> 10;
            int n = (i >> 2) & 255;
            int seg = i & 3;
            uint32_t sa = smb + B_OFF + buf * BBUF + split * BSPLIT +
                          n * BROW + seg * 16;
            cp16(sa, &Wbf[L][split][n][kc * 32 + seg * 8]);
        }
        CP_COMMIT();
    };

    auto storeA = [&](int m, int k, float v) {
        __nv_bfloat16 h = __float2bfloat16(v);
        __nv_bfloat16 l = __float2bfloat16(v - __bfloat162float(h));
        char* base = sm + A_OFF + m * AROW + k * 2;
        *(__nv_bfloat16*)(base)       = h;
        *(__nv_bfloat16*)(base + 528) = l;
    };

    // prefetch first two B stages of layer 0 (ring slots 0,1)
    issue_stage(0, 0, 0);
    issue_stage(0, 1, 1);

    // coords
    if (tid < 76) {
        int ss = tid >> 2, w = tid & 3;
        int n = n0 + ss; if (n >= N) n = N - 1;
        const float* p = (w == 0) ? gx : (w == 1) ? gy : (w == 2) ? gz : gf;
        xyzf[tid] = p[n];
    }
    // zero pad row 95 of A (both splits)
    if (tid < 256) storeA(95, tid, 0.0f);
    __syncthreads();

    // ---- layer 1: 4 -> 256, jets analytically ------------------------------
    #pragma unroll 1
    for (int it = 0; it < 10; ++it) {
        int idx = tid + (it << 9);               // 19*256 = 4864 items
        if (idx < SB * 256) {
            int s = idx >> 8, k = idx & 255;
            float4 w = *(const float4*)(W1 + k * 4);
            float u = fmaf(w.x, xyzf[s * 4 + 0], fmaf(w.y, xyzf[s * 4 + 1],
                      fmaf(w.z, xyzf[s * 4 + 2], fmaf(w.w, xyzf[s * 4 + 3],
                      b1[k]))));
            float yv = tanhf(u);
            float sg = fmaf(-yv, yv, 1.0f);
            float g  = CX * w.x * w.x + CY * w.y * w.y + CZ * w.z * w.z;
            int m = s * 5;
            storeA(m + 0, k, yv);
            storeA(m + 1, k, sg * w.x);
            storeA(m + 2, k, sg * w.y);
            storeA(m + 3, k, sg * w.z);
            storeA(m + 4, k, -2.0f * yv * sg * g);
        }
    }
    __syncthreads();

    const int g = lid >> 2, cc = (lid & 3) << 1;

    // ---- hidden layers 2,3 --------------------------------------------------
    #pragma unroll 1
    for (int L = 0; L < 2; ++L) {
        float acc[MT][4][4];
        #pragma unroll
        for (int mt = 0; mt < MT; ++mt)
            #pragma unroll
            for (int nt = 0; nt < 4; ++nt)
                #pragma unroll
                for (int r = 0; r < 4; ++r) acc[mt][nt][r] = 0.f;

        #pragma unroll 1
        for (int kc = 0; kc < NKC; ++kc) {
            int gi = L * NKC + kc;
            if (gi == 2 * NKC - 1) { CP_WAIT(0); } else { CP_WAIT(1); }
            __syncthreads();                     // stage gi ready for all;
                                                 // all warps past chunk gi-1
            // refill ring slot (gi+2)%3 (last read at chunk gi-1)
            if (kc + 2 < NKC)    issue_stage(L, kc + 2, (gi + 2) % 3);
            else if (L == 0)     issue_stage(1, kc - (NKC - 2), (gi + 2) % 3);

            int buf = gi % 3;
            #pragma unroll
            for (int ks = 0; ks < 2; ++ks) {
                int kl0 = ks << 4;
                uint32_t bf[2][4][2];
                #pragma unroll
                for (int nt = 0; nt < 4; ++nt) {
                    uint32_t ba = smb + B_OFF + buf * BBUF +
                                  (n0w + (nt << 3) + (lid & 7)) * BROW +
                                  (kl0 + (lid & 8)) * 2;
                    ldsm2(bf[0][nt], ba);
                    ldsm2(bf[1][nt], ba + BSPLIT);
                }
                #pragma unroll
                for (int mt = 0; mt < MT; ++mt) {
                    int row = mg * 48 + (mt << 4) + (lid & 15);
                    uint32_t aa = smb + A_OFF + row * AROW +
                                  (kc * 32 + kl0 + ((lid >> 4) << 3)) * 2;
                    uint32_t ah[4], al[4];
                    ldsm4(ah, aa);
                    ldsm4(al, aa + 528);
                    #pragma unroll
                    for (int nt = 0; nt < 4; ++nt) {
                        mma_bf16(acc[mt][nt], ah, bf[0][nt]);  // hi*hi
                        mma_bf16(acc[mt][nt], al, bf[0][nt]);  // lo*hi
                        mma_bf16(acc[mt][nt], ah, bf[1][nt]);  // hi*lo
                    }
                }
            }
        }
        __syncthreads();   // all MMA reads of A done before D overwrites A

        // ---- stage acc into D (aliases dead A rows) --------------------------
        #pragma unroll
        for (int mt = 0; mt < MT; ++mt)
            #pragma unroll
            for (int nt = 0; nt < 4; ++nt) {
                int m0 = mg * 48 + (mt << 4), nn = n0w + (nt << 3) + cc;
                *(float2*)(Dst + (m0 + g) * DROW + nn) =
                    make_float2(acc[mt][nt][0], acc[mt][nt][1]);
                *(float2*)(Dst + (m0 + g + 8) * DROW + nn) =
                    make_float2(acc[mt][nt][2], acc[mt][nt][3]);
            }
        __syncthreads();

        // ---- activation epilogue (in-place D -> new A exchange) --------------
        const int sg2 = tid >> 8;          // sample group 0/1
        const int nn  = tid & 255;
        if (L == 0) {
            float bn = b2[nn];
            #pragma unroll 1
            for (int s10 = 0; s10 < 10; ++s10) {
                int s = sg2 * 10 + s10;
                bool ok = (s < SB);
                int mr = s * 5;
                float u = 0.f, tx = 0.f, ty = 0.f, tz = 0.f, qa = 0.f;
                if (ok) {
                    u  = Dst[(mr + 0) * DROW + nn] + bn;
                    tx = Dst[(mr + 1) * DROW + nn];
                    ty = Dst[(mr + 2) * DROW + nn];
                    tz = Dst[(mr + 3) * DROW + nn];
                    qa = Dst[(mr + 4) * DROW + nn];
                }
                __syncthreads();           // all reads of these rows done
                if (ok) {
                    float yv = tanhf(u);
                    float sgm = fmaf(-yv, yv, 1.0f);
                    float gq = CX * tx * tx + CY * ty * ty + CZ * tz * tz;
                    storeA(mr + 0, nn, yv);
                    storeA(mr + 1, nn, sgm * tx);
                    storeA(mr + 2, nn, sgm * ty);
                    storeA(mr + 3, nn, sgm * tz);
                    storeA(mr + 4, nn, fmaf(sgm, qa, -2.0f * yv * sgm * gq));
                }
            }
            __syncthreads();
        } else {
            float bn  = b3[nn];
            float w40 = W4[nn], w41 = W4[HD + nn];
            #pragma unroll 1
            for (int s10 = 0; s10 < 10; ++s10) {
                int s = sg2 * 10 + s10;
                if (s < SB) {
                    int mr = s * 5;
                    float u  = Dst[(mr + 0) * DROW + nn] + bn;
                    float tx = Dst[(mr + 1) * DROW + nn];
                    float ty = Dst[(mr + 2) * DROW + nn];
                    float tz = Dst[(mr + 3) * DROW + nn];
                    float qa = Dst[(mr + 4) * DROW + nn];
                    float yv = tanhf(u);
                    float sgm = fmaf(-yv, yv, 1.0f);
                    float gq = CX * tx * tx + CY * ty * ty + CZ * tz * tz;
                    float qn = fmaf(sgm, qa, -2.0f * yv * sgm * gq);
                    float v0 = w40 * yv, v1 = w41 * yv;
                    float v2 = w40 * qn, v3 = w41 * qn;
                    #pragma unroll
                    for (int o = 16; o; o >>= 1) {
                        v0 += __shfl_xor_sync(0xFFFFFFFFu, v0, o);
                        v1 += __shfl_xor_sync(0xFFFFFFFFu, v1, o);
                        v2 += __shfl_xor_sync(0xFFFFFFFFu, v2, o);
                        v3 += __shfl_xor_sync(0xFFFFFFFFu, v3, o);
                    }
                    if (lid == 0) {
                        float* pp = part + (s * 8 + (wid & 7)) * 4;
                        pp[0] = v0; pp[1] = v1; pp[2] = v2; pp[3] = v3;
                    }
                }
            }
            __syncthreads();
        }
    }

    // ---- residual output -----------------------------------------------------
    if (tid < SB) {
        int n = n0 + tid;
        if (n < N) {
            float P0 = 0.f, P1 = 0.f, Q0 = 0.f, Q1 = 0.f;
            #pragma unroll
            for (int w = 0; w < 8; ++w) {
                const float* pp = part + (tid * 8 + w) * 4;
                P0 += pp[0]; P1 += pp[1]; Q0 += pp[2]; Q1 += pp[3];
            }
            P0 += b4[0]; P1 += b4[1];
            float fs = xyzf[tid * 4 + 3];
            float kw = 6.283185307179586f * fmaf(fs, 500.0f, 100.0f) / 343.0f;
            float kx = 0.21f * kw;
            float K2 = kx * kx;
            out[n]     = 2.0f * Q0 + K2 * fmaf(2.0f, P0, 0.1f);
            out[N + n] = 1.5f * Q1 + K2 * fmaf(1.5f, P1, -0.05f);
        }
    }
}

extern "C" void kernel_launch(void* const* d_in, const int* in_sizes, int n_in,
                              void* d_out, int out_size)
{
    const float* x  = (const float*)d_in[0];
    const float* y  = (const float*)d_in[1];
    const float* z  = (const float*)d_in[2];
    const float* f  = (const float*)d_in[3];
    const float* W1 = (const float*)d_in[4];
    const float* b1 = (const float*)d_in[5];
    const float* W2 = (const float*)d_in[6];
    const float* b2 = (const float*)d_in[7];
    const float* W3 = (const float*)d_in[8];
    const float* b3 = (const float*)d_in[9];
    const float* W4 = (const float*)d_in[10];
    const float* b4 = (const float*)d_in[11];
    float* out = (float*)d_out;

    int N = in_sizes[0];
    prep_weights<<<512, 256>>>(W2, W3);

    cudaFuncSetAttribute(bvp_mma_kernel,
                         cudaFuncAttributeMaxDynamicSharedMemorySize,
                         SMEM_BYTES);
    int blocks = (N + SB - 1) / SB;
    bvp_mma_kernel<<<blocks, 512, SMEM_BYTES>>>(x, y, z, f, W1, b1, b2, b3,
                                                W4, b4, out, N);
}

// round 8
// speedup vs baseline: 1.4164x; 1.1032x over previous
#include <cuda_runtime.h>
#include <cuda_bf16.h>
#include <cstdint>

// ---------------------------------------------------------------------------
// BVP Helmholtz residual via 2nd-order jet propagation on mma.sync bf16 HMMA
// (3-pass hi/lo split). Round 8 = round 5 geometry (512 thr, M=128,
// 24 samples/CTA) + fast MUFU-based tanh + 1 barrier per k-chunk +
// batched in-place epilogue (3 barriers instead of 12).
// ---------------------------------------------------------------------------

#define HD 256
#define SB 24          // samples per CTA
#define AROW 1040      // A row bytes: hi[0,512) pad lo[528,1040)  == D row
#define BROW 80        // B stage row stride bytes
#define BSPLIT 20480   // 256*80
#define BBUF 40960     // 2 splits
#define DROW 260       // D row stride in floats (= 1040 B)

#define A_OFF 0
#define B_OFF 133120   // 128*1040
#define XYZF_OFF 215040
#define PART_OFF 215424
#define SMEM_BYTES 218624

// prepped weights: [layer][split hi/lo][n][k] bf16
__device__ __align__(16) __nv_bfloat16 Wbf[2][2][HD][HD];

__global__ __launch_bounds__(256)
void prep_weights(const float* __restrict__ W2, const float* __restrict__ W3)
{
    int t = blockIdx.x * 256 + threadIdx.x;      // 131072
    int layer = t >> 16, n = (t >> 8) & 255, k = t & 255;
    float w = (layer ? W3 : W2)[n * HD + k];
    __nv_bfloat16 h = __float2bfloat16(w);
    __nv_bfloat16 l = __float2bfloat16(w - __bfloat162float(h));
    Wbf[layer][0][n][k] = h;
    Wbf[layer][1][n][k] = l;
}

__device__ __forceinline__ uint32_t smem_u32(const void* p) {
    uint32_t a;
    asm("{ .reg .u64 t; cvta.to.shared.u64 t, %1; cvt.u32.u64 %0, t; }"
        : "=r"(a) : "l"(p));
    return a;
}
__device__ __forceinline__ void ldsm4(uint32_t* r, uint32_t a) {
    asm volatile("ldmatrix.sync.aligned.m8n8.x4.shared.b16 {%0,%1,%2,%3}, [%4];"
                 : "=r"(r[0]), "=r"(r[1]), "=r"(r[2]), "=r"(r[3]) : "r"(a));
}
__device__ __forceinline__ void ldsm2(uint32_t* r, uint32_t a) {
    asm volatile("ldmatrix.sync.aligned.m8n8.x2.shared.b16 {%0,%1}, [%2];"
                 : "=r"(r[0]), "=r"(r[1]) : "r"(a));
}
__device__ __forceinline__ void mma_bf16(float* c, const uint32_t* a,
                                         const uint32_t* b) {
    asm volatile("mma.sync.aligned.m16n8k16.row.col.f32.bf16.bf16.f32 "
                 "{%0,%1,%2,%3}, {%4,%5,%6,%7}, {%8,%9}, {%0,%1,%2,%3};"
                 : "+f"(c[0]), "+f"(c[1]), "+f"(c[2]), "+f"(c[3])
                 : "r"(a[0]), "r"(a[1]), "r"(a[2]), "r"(a[3]),
                   "r"(b[0]), "r"(b[1]));
}
__device__ __forceinline__ void cp16(uint32_t sa, const void* ga) {
    asm volatile("cp.async.cg.shared.global [%0], [%1], 16;"
                 :: "r"(sa), "l"(__cvta_generic_to_global(ga)) : "memory");
}
#define CP_COMMIT() asm volatile("cp.async.commit_group;" ::: "memory")
#define CP_WAIT(n)  asm volatile("cp.async.wait_group %0;" :: "n"(n) : "memory")

// fast tanh: 1 - 2/(exp(2u)+1). abs err ~3e-7, handles +-inf correctly.
__device__ __forceinline__ float ftanh(float u) {
    float e = __expf(2.0f * u);
    return 1.0f - __fdividef(2.0f, e + 1.0f);
}

__global__ __launch_bounds__(512, 1)
void bvp_mma_kernel(const float* __restrict__ gx, const float* __restrict__ gy,
                    const float* __restrict__ gz, const float* __restrict__ gf,
                    const float* __restrict__ W1, const float* __restrict__ b1,
                    const float* __restrict__ b2, const float* __restrict__ b3,
                    const float* __restrict__ W4, const float* __restrict__ b4,
                    float* __restrict__ out, int N)
{
    extern __shared__ char sm[];
    const uint32_t smb = smem_u32(sm);
    float* Dst  = (float*)(sm + A_OFF);       // aliases A region, row-for-row
    float* xyzf = (float*)(sm + XYZF_OFF);
    float* part = (float*)(sm + PART_OFF);    // [24][8][4]

    const int tid = threadIdx.x;
    const int wid = tid >> 5;
    const int lid = tid & 31;
    const int mg  = wid >> 3;                 // m-group 0/1 (rows mg*64..+64)
    const int ng  = wid & 7;                  // n-slice (cols ng*32..+32)
    const int n0w = ng << 5;
    const int n0  = blockIdx.x * SB;

    const float CX = (float)((0.5 * 0.6) * (0.5 * 0.6));
    const float CY = (float)((0.7 * 0.6) * (0.7 * 0.6));
    const float CZ = (float)((0.7 * 0.5) * (0.7 * 0.5));

    auto issue_stage = [&](int L, int kc, int buf) {
        #pragma unroll
        for (int j = 0; j < 4; ++j) {
            int i = tid + (j << 9);              // 0..2047
            int split = i >> 10;
            int n = (i >> 2) & 255;
            int seg = i & 3;
            uint32_t sa = smb + B_OFF + buf * BBUF + split * BSPLIT +
                          n * BROW + seg * 16;
            cp16(sa, &Wbf[L][split][n][kc * 32 + seg * 8]);
        }
        CP_COMMIT();
    };

    auto storeA = [&](int m, int k, float v) {
        __nv_bfloat16 h = __float2bfloat16(v);
        __nv_bfloat16 l = __float2bfloat16(v - __bfloat162float(h));
        char* base = sm + A_OFF + m * AROW + k * 2;
        *(__nv_bfloat16*)(base)       = h;
        *(__nv_bfloat16*)(base + 528) = l;
    };

    // prefetch first B stage of layer 0
    issue_stage(0, 0, 0);

    // coords
    if (tid < 96) {
        int ss = tid >> 2, w = tid & 3;
        int n = n0 + ss; if (n >= N) n = N - 1;
        const float* p = (w == 0) ? gx : (w == 1) ? gy : (w == 2) ? gz : gf;
        xyzf[tid] = p[n];
    }
    __syncthreads();

    // ---- layer 1: 4 -> 256, jets analytically ------------------------------
    #pragma unroll 1
    for (int it = 0; it < 12; ++it) {
        int idx = tid + (it << 9);               // 24*256 = 6144 items
        int s = idx >> 8, k = idx & 255;
        float4 w = *(const float4*)(W1 + k * 4);
        float u = fmaf(w.x, xyzf[s * 4 + 0], fmaf(w.y, xyzf[s * 4 + 1],
                  fmaf(w.z, xyzf[s * 4 + 2], fmaf(w.w, xyzf[s * 4 + 3],
                  b1[k]))));
        float yv = ftanh(u);
        float sg = fmaf(-yv, yv, 1.0f);
        float g  = CX * w.x * w.x + CY * w.y * w.y + CZ * w.z * w.z;
        int m = s * 5;
        storeA(m + 0, k, yv);
        storeA(m + 1, k, sg * w.x);
        storeA(m + 2, k, sg * w.y);
        storeA(m + 3, k, sg * w.z);
        storeA(m + 4, k, -2.0f * yv * sg * g);
    }

    const int g = lid >> 2, cc = (lid & 3) << 1;

    // ---- hidden layers 2,3 --------------------------------------------------
    #pragma unroll 1
    for (int L = 0; L < 2; ++L) {
        float acc[4][4][4];
        #pragma unroll
        for (int mt = 0; mt < 4; ++mt)
            #pragma unroll
            for (int nt = 0; nt < 4; ++nt)
                #pragma unroll
                for (int r = 0; r < 4; ++r) acc[mt][nt][r] = 0.f;

        #pragma unroll 1
        for (int kc = 0; kc < 8; ++kc) {
            int gi = L * 8 + kc;
            CP_WAIT(0);
            __syncthreads();   // stage gi ready everywhere; all warps are past
                               // chunk gi-1's reads of buffer (gi+1)&1
            if (gi + 1 < 16) {
                int nl = (gi + 1) >> 3, nkc = (gi + 1) & 7;
                issue_stage(nl, nkc, (gi + 1) & 1);
            }
            int buf = gi & 1;

            #pragma unroll
            for (int ks = 0; ks < 2; ++ks) {
                int kl0 = ks << 4;
                uint32_t bf[2][4][2];
                #pragma unroll
                for (int nt = 0; nt < 4; ++nt) {
                    uint32_t ba = smb + B_OFF + buf * BBUF +
                                  (n0w + (nt << 3) + (lid & 7)) * BROW +
                                  (kl0 + (lid & 8)) * 2;
                    ldsm2(bf[0][nt], ba);
                    ldsm2(bf[1][nt], ba + BSPLIT);
                }
                #pragma unroll
                for (int mt = 0; mt < 4; ++mt) {
                    int row = (mg << 6) + (mt << 4) + (lid & 15);
                    uint32_t aa = smb + A_OFF + row * AROW +
                                  (kc * 32 + kl0 + ((lid >> 4) << 3)) * 2;
                    uint32_t ah[4], al[4];
                    ldsm4(ah, aa);
                    ldsm4(al, aa + 528);
                    #pragma unroll
                    for (int nt = 0; nt < 4; ++nt) {
                        mma_bf16(acc[mt][nt], ah, bf[0][nt]);  // hi*hi
                        mma_bf16(acc[mt][nt], al, bf[0][nt]);  // lo*hi
                        mma_bf16(acc[mt][nt], ah, bf[1][nt]);  // hi*lo
                    }
                }
            }
        }
        __syncthreads();   // all MMA reads of A done before D overwrites A

        // ---- stage acc into D (aliases dead A rows) --------------------------
        #pragma unroll
        for (int mt = 0; mt < 4; ++mt)
            #pragma unroll
            for (int nt = 0; nt < 4; ++nt) {
                int m0 = (mg << 6) + (mt << 4), nn = n0w + (nt << 3) + cc;
                *(float2*)(Dst + (m0 + g) * DROW + nn) =
                    make_float2(acc[mt][nt][0], acc[mt][nt][1]);
                *(float2*)(Dst + (m0 + g + 8) * DROW + nn) =
                    make_float2(acc[mt][nt][2], acc[mt][nt][3]);
            }
        __syncthreads();

        // ---- activation epilogue --------------------------------------------
        const int sg2 = tid >> 8;          // sample group 0/1
        const int nn  = tid & 255;
        if (L == 0) {
            // in-place D -> new A exchange, batched 4 samples per barrier
            float bn = b2[nn];
            #pragma unroll 1
            for (int bb = 0; bb < 3; ++bb) {
                float t5[4][5];
                #pragma unroll
                for (int j = 0; j < 4; ++j) {
                    int mr = (sg2 * 12 + bb * 4 + j) * 5;
                    #pragma unroll
                    for (int c = 0; c < 5; ++c)
                        t5[j][c] = Dst[(mr + c) * DROW + nn];
                }
                __syncthreads();           // all reads of these rows done
                #pragma unroll
                for (int j = 0; j < 4; ++j) {
                    int mr = (sg2 * 12 + bb * 4 + j) * 5;
                    float yv = ftanh(t5[j][0] + bn);
                    float sgm = fmaf(-yv, yv, 1.0f);
                    float gq = CX * t5[j][1] * t5[j][1] +
                               CY * t5[j][2] * t5[j][2] +
                               CZ * t5[j][3] * t5[j][3];
                    storeA(mr + 0, nn, yv);
                    storeA(mr + 1, nn, sgm * t5[j][1]);
                    storeA(mr + 2, nn, sgm * t5[j][2]);
                    storeA(mr + 3, nn, sgm * t5[j][3]);
                    storeA(mr + 4, nn, fmaf(sgm, t5[j][4],
                                            -2.0f * yv * sgm * gq));
                }
            }
            __syncthreads();
        } else {
            float bn  = b3[nn];
            float w40 = W4[nn], w41 = W4[HD + nn];
            #pragma unroll 1
            for (int s12 = 0; s12 < 12; ++s12) {
                int s = sg2 * 12 + s12, mr = s * 5;
                float u  = Dst[(mr + 0) * DROW + nn] + bn;
                float tx = Dst[(mr + 1) * DROW + nn];
                float ty = Dst[(mr + 2) * DROW + nn];
                float tz = Dst[(mr + 3) * DROW + nn];
                float qa = Dst[(mr + 4) * DROW + nn];
                float yv = ftanh(u);
                float sgm = fmaf(-yv, yv, 1.0f);
                float gq = CX * tx * tx + CY * ty * ty + CZ * tz * tz;
                float qn = fmaf(sgm, qa, -2.0f * yv * sgm * gq);
                float v0 = w40 * yv, v1 = w41 * yv;
                float v2 = w40 * qn, v3 = w41 * qn;
                #pragma unroll
                for (int o = 16; o; o >>= 1) {
                    v0 += __shfl_xor_sync(0xFFFFFFFFu, v0, o);
                    v1 += __shfl_xor_sync(0xFFFFFFFFu, v1, o);
                    v2 += __shfl_xor_sync(0xFFFFFFFFu, v2, o);
                    v3 += __shfl_xor_sync(0xFFFFFFFFu, v3, o);
                }
                if (lid == 0) {
                    float* pp = part + (s * 8 + (wid & 7)) * 4;
                    pp[0] = v0; pp[1] = v1; pp[2] = v2; pp[3] = v3;
                }
            }
            __syncthreads();
        }
    }

    // ---- residual output -----------------------------------------------------
    if (tid < SB) {
        int n = n0 + tid;
        if (n < N) {
            float P0 = 0.f, P1 = 0.f, Q0 = 0.f, Q1 = 0.f;
            #pragma unroll
            for (int w = 0; w < 8; ++w) {
                const float* pp = part + (tid * 8 + w) * 4;
                P0 += pp[0]; P1 += pp[1]; Q0 += pp[2]; Q1 += pp[3];
            }
            P0 += b4[0]; P1 += b4[1];
            float fs = xyzf[tid * 4 + 3];
            float kw = 6.283185307179586f * fmaf(fs, 500.0f, 100.0f) / 343.0f;
            float kx = 0.21f * kw;
            float K2 = kx * kx;
            out[n]     = 2.0f * Q0 + K2 * fmaf(2.0f, P0, 0.1f);
            out[N + n] = 1.5f * Q1 + K2 * fmaf(1.5f, P1, -0.05f);
        }
    }
}

extern "C" void kernel_launch(void* const* d_in, const int* in_sizes, int n_in,
                              void* d_out, int out_size)
{
    const float* x  = (const float*)d_in[0];
    const float* y  = (const float*)d_in[1];
    const float* z  = (const float*)d_in[2];
    const float* f  = (const float*)d_in[3];
    const float* W1 = (const float*)d_in[4];
    const float* b1 = (const float*)d_in[5];
    const float* W2 = (const float*)d_in[6];
    const float* b2 = (const float*)d_in[7];
    const float* W3 = (const float*)d_in[8];
    const float* b3 = (const float*)d_in[9];
    const float* W4 = (const float*)d_in[10];
    const float* b4 = (const float*)d_in[11];
    float* out = (float*)d_out;

    int N = in_sizes[0];
    prep_weights<<<512, 256>>>(W2, W3);

    cudaFuncSetAttribute(bvp_mma_kernel,
                         cudaFuncAttributeMaxDynamicSharedMemorySize,
                         SMEM_BYTES);
    int blocks = (N + SB - 1) / SB;
    bvp_mma_kernel<<<blocks, 512, SMEM_BYTES>>>(x, y, z, f, W1, b1, b2, b3,
                                                W4, b4, out, N);
}